// round 3
// baseline (speedup 1.0000x reference)
#include <cuda_runtime.h>
#include <cuda_bf16.h>
#include <math.h>
#include <float.h>

#define DIM 1024
#define NUM_HEADS 16
#define NUM_KV_HEADS 4
#define HEAD_DIM 64
#define KV_DIM (NUM_KV_HEADS * HEAD_DIM)   // 256
#define PARTIAL_ROPE_DIM 32
#define LORA_RANK 4
#define NUM_LORA_STEPS 2
#define BATCH 2
#define SEQ 2048
#define MTOT (BATCH * SEQ)                 // 4096

// ---------------- scratch (no allocs allowed) ----------------
__device__ float g_q[MTOT * DIM];
__device__ float g_k[MTOT * KV_DIM];
__device__ float g_v[MTOT * KV_DIM];
__device__ float g_y[MTOT * DIM];
__device__ float g_tq[MTOT * LORA_RANK];
__device__ float g_tv[MTOT * LORA_RANK];

// ---------------- SGEMM: C[M,N] = A[M,K] @ B[N,K]^T ----------------
#define BM 64
#define BN 64
#define BK 16

__global__ void __launch_bounds__(256)
sgemm_abt(const float* __restrict__ A, const float* __restrict__ B,
          float* __restrict__ C, int M, int N, int K) {
    __shared__ float As[BK][BM];
    __shared__ float Bs[BK][BN];
    const int tid = threadIdx.x;
    const int tx = tid & 15, ty = tid >> 4;
    const int m0 = blockIdx.y * BM, n0 = blockIdx.x * BN;

    const int lrow = tid >> 2;        // 0..63
    const int lk   = (tid & 3) * 4;   // 0,4,8,12

    float acc[4][4];
#pragma unroll
    for (int i = 0; i < 4; i++)
#pragma unroll
        for (int j = 0; j < 4; j++) acc[i][j] = 0.f;

    for (int k0 = 0; k0 < K; k0 += BK) {
        float4 a4 = *(const float4*)&A[(size_t)(m0 + lrow) * K + k0 + lk];
        float4 b4 = *(const float4*)&B[(size_t)(n0 + lrow) * K + k0 + lk];
        As[lk + 0][lrow] = a4.x; As[lk + 1][lrow] = a4.y;
        As[lk + 2][lrow] = a4.z; As[lk + 3][lrow] = a4.w;
        Bs[lk + 0][lrow] = b4.x; Bs[lk + 1][lrow] = b4.y;
        Bs[lk + 2][lrow] = b4.z; Bs[lk + 3][lrow] = b4.w;
        __syncthreads();
#pragma unroll
        for (int kk = 0; kk < BK; kk++) {
            float ra[4], rb[4];
#pragma unroll
            for (int i = 0; i < 4; i++) ra[i] = As[kk][ty * 4 + i];
#pragma unroll
            for (int j = 0; j < 4; j++) rb[j] = Bs[kk][tx * 4 + j];
#pragma unroll
            for (int i = 0; i < 4; i++)
#pragma unroll
                for (int j = 0; j < 4; j++) acc[i][j] = fmaf(ra[i], rb[j], acc[i][j]);
        }
        __syncthreads();
    }
#pragma unroll
    for (int i = 0; i < 4; i++)
#pragma unroll
        for (int j = 0; j < 4; j++)
            C[(size_t)(m0 + ty * 4 + i) * N + n0 + tx * 4 + j] = acc[i][j];
}

// ---------------- LoRA down: t[M,R] = x[M,K] @ A[step][R,K]^T ----------------
__global__ void lora_down(const float* __restrict__ x, const float* __restrict__ Aall,
                          const int* __restrict__ step_ptr, float* __restrict__ t, int K) {
    const int m = blockIdx.x;
    const int warp = threadIdx.x >> 5, lane = threadIdx.x & 31;
    const int step = *step_ptr;
    if (step < 0 || step >= NUM_LORA_STEPS) {
        if (lane == 0) t[m * LORA_RANK + warp] = 0.f;
        return;
    }
    const float* Arow = Aall + ((size_t)step * LORA_RANK + warp) * K;
    const float* xrow = x + (size_t)m * K;
    float s = 0.f;
    for (int k = lane; k < K; k += 32) s = fmaf(xrow[k], Arow[k], s);
#pragma unroll
    for (int o = 16; o; o >>= 1) s += __shfl_xor_sync(0xffffffffu, s, o);
    if (lane == 0) t[m * LORA_RANK + warp] = s;
}

// ---------------- LoRA up: C[M,N] += scale * t[M,R] @ B[step][N,R]^T ----------------
__global__ void lora_up(const float* __restrict__ t, const float* __restrict__ Ball,
                        const int* __restrict__ step_ptr, float* __restrict__ C,
                        int M, int N, float scale) {
    const int step = *step_ptr;
    if (step < 0 || step >= NUM_LORA_STEPS) return;
    const float* Bm = Ball + (size_t)step * N * LORA_RANK;
    int i = blockIdx.x * blockDim.x + threadIdx.x;
    if (i >= M * N) return;
    int m = i / N, n = i - m * N;
    const float* tm = t + (size_t)m * LORA_RANK;
    const float* bn = Bm + (size_t)n * LORA_RANK;
    float acc = tm[0] * bn[0] + tm[1] * bn[1] + tm[2] * bn[2] + tm[3] * bn[3];
    C[i] += scale * acc;
}

// ---------------- RMSNorm + partial RoPE + gain (warp per (token, head)) -------
__global__ void rmsnorm_rope(float* __restrict__ data, const float* __restrict__ gain,
                             int n_heads, int total_rows) {
    const int g = blockIdx.x * (blockDim.x >> 5) + (threadIdx.x >> 5);
    if (g >= total_rows) return;
    const int lane = threadIdx.x & 31;
    const int h = g % n_heads;
    const int token = g / n_heads;
    const int s = token % SEQ;
    float* row = data + (size_t)token * n_heads * HEAD_DIM + h * HEAD_DIM;
    float v0 = row[lane];
    float v1 = row[lane + 32];
    float ss = v0 * v0 + v1 * v1;
#pragma unroll
    for (int o = 16; o; o >>= 1) ss += __shfl_xor_sync(0xffffffffu, ss, o);
    float r = rsqrtf(ss * (1.0f / 64.0f) + 1.1920929e-7f);
    v0 *= r; v1 *= r;
    // partial RoPE on dims [0,32): pairs (i, i+16)
    float other = __shfl_xor_sync(0xffffffffu, v0, 16);
    int fi = lane & 15;
    float inv_freq = powf(10000.0f, -(float)(2 * fi) / (float)PARTIAL_ROPE_DIM);
    float ang = (float)s * inv_freq;
    float c = cosf(ang), sn = sinf(ang);
    float out;
    if (lane < 16) out = v0 * c + other * sn;      // x1*c + x2*s
    else           out = -other * sn + v0 * c;     // -x1*s + x2*c
    v0 = out;
    float gq = gain ? gain[h] : 1.0f;
    row[lane]      = v0 * gq;
    row[lane + 32] = v1 * gq;
}

// ---------------- causal flash attention, 64-row Q tile per block ----------------
// grid: (S/64, NUM_HEADS, B), 256 threads, dyn smem = 3*64*64*4 = 48KB
__global__ void __launch_bounds__(256)
attn_kernel(const float* __restrict__ q, const float* __restrict__ k,
            const float* __restrict__ v, float* __restrict__ y) {
    extern __shared__ float sm[];
    float* q_s  = sm;               // [64][64]
    float* kp_s = sm + 64 * 64;     // K tile, then reused for P
    float* v_s  = sm + 2 * 64 * 64; // [64][64]

    const int mt = blockIdx.x, h = blockIdx.y, b = blockIdx.z;
    const int kh = h / (NUM_HEADS / NUM_KV_HEADS);
    const int tid = threadIdx.x;
    const int tx = tid & 15, ty = tid >> 4;
    const int m0 = mt * 64;
    const float scale = 0.125f;  // 1/sqrt(64)

    const size_t qbase = ((size_t)b * SEQ + m0) * DIM + h * HEAD_DIM;
    for (int i = tid; i < 64 * 64; i += 256) {
        int r = i >> 6, d = i & 63;
        q_s[i] = q[qbase + (size_t)r * DIM + d];
    }

    float o[4][4];
    float mrow[4], lrow[4];
#pragma unroll
    for (int i = 0; i < 4; i++) {
        mrow[i] = -INFINITY; lrow[i] = 0.f;
#pragma unroll
        for (int j = 0; j < 4; j++) o[i][j] = 0.f;
    }

    for (int kt = 0; kt <= mt; kt++) {
        const int c0 = kt * 64;
        __syncthreads();
        for (int i = tid; i < 64 * 64; i += 256) {
            int r = i >> 6, d = i & 63;
            size_t base = ((size_t)b * SEQ + c0 + r) * KV_DIM + kh * HEAD_DIM + d;
            kp_s[i] = k[base];
            v_s[i]  = v[base];
        }
        __syncthreads();

        float s[4][4];
#pragma unroll
        for (int i = 0; i < 4; i++)
#pragma unroll
            for (int j = 0; j < 4; j++) s[i][j] = 0.f;

        for (int kd = 0; kd < 64; kd++) {
            float ra[4], rb[4];
#pragma unroll
            for (int i = 0; i < 4; i++) ra[i] = q_s[(ty * 4 + i) * 64 + kd];
#pragma unroll
            for (int j = 0; j < 4; j++) rb[j] = kp_s[(tx * 4 + j) * 64 + kd];
#pragma unroll
            for (int i = 0; i < 4; i++)
#pragma unroll
                for (int j = 0; j < 4; j++) s[i][j] = fmaf(ra[i], rb[j], s[i][j]);
        }

        const bool diag = (kt == mt);
#pragma unroll
        for (int i = 0; i < 4; i++) {
            int qr = m0 + ty * 4 + i;
#pragma unroll
            for (int j = 0; j < 4; j++) {
                float val = s[i][j] * scale;
                if (diag && (c0 + tx * 4 + j) > qr) val = -INFINITY;
                s[i][j] = val;
            }
        }

        float p[4][4];
#pragma unroll
        for (int i = 0; i < 4; i++) {
            float rmax = fmaxf(fmaxf(s[i][0], s[i][1]), fmaxf(s[i][2], s[i][3]));
#pragma unroll
            for (int o2 = 8; o2; o2 >>= 1)
                rmax = fmaxf(rmax, __shfl_xor_sync(0xffffffffu, rmax, o2));
            float newm = fmaxf(mrow[i], rmax);
            float alpha = __expf(mrow[i] - newm);
            float rsum = 0.f;
#pragma unroll
            for (int j = 0; j < 4; j++) {
                p[i][j] = __expf(s[i][j] - newm);
                rsum += p[i][j];
            }
#pragma unroll
            for (int o2 = 8; o2; o2 >>= 1)
                rsum += __shfl_xor_sync(0xffffffffu, rsum, o2);
            lrow[i] = lrow[i] * alpha + rsum;
#pragma unroll
            for (int j = 0; j < 4; j++) o[i][j] *= alpha;
            mrow[i] = newm;
        }

        __syncthreads();  // everyone done reading K tile
#pragma unroll
        for (int i = 0; i < 4; i++)
#pragma unroll
            for (int j = 0; j < 4; j++)
                kp_s[(ty * 4 + i) * 64 + tx * 4 + j] = p[i][j];
        __syncthreads();

        for (int c = 0; c < 64; c++) {
            float rp[4], rv[4];
#pragma unroll
            for (int i = 0; i < 4; i++) rp[i] = kp_s[(ty * 4 + i) * 64 + c];
#pragma unroll
            for (int j = 0; j < 4; j++) rv[j] = v_s[c * 64 + tx * 4 + j];
#pragma unroll
            for (int i = 0; i < 4; i++)
#pragma unroll
                for (int j = 0; j < 4; j++) o[i][j] = fmaf(rp[i], rv[j], o[i][j]);
        }
    }

#pragma unroll
    for (int i = 0; i < 4; i++) {
        float inv_l = 1.0f / lrow[i];
#pragma unroll
        for (int j = 0; j < 4; j++)
            y[((size_t)b * SEQ + m0 + ty * 4 + i) * DIM + h * HEAD_DIM + tx * 4 + j] =
                o[i][j] * inv_l;
    }
}

// ---------------- launch ----------------
extern "C" void kernel_launch(void* const* d_in, const int* in_sizes, int n_in,
                              void* d_out, int out_size) {
    const float* x     = (const float*)d_in[0];
    const float* Wq    = (const float*)d_in[1];
    const float* Wk    = (const float*)d_in[2];
    const float* Wv    = (const float*)d_in[3];
    const float* Wproj = (const float*)d_in[4];
    const float* qgain = (const float*)d_in[5];
    const float* lAq   = (const float*)d_in[6];
    const float* lBq   = (const float*)d_in[7];
    const float* lAv   = (const float*)d_in[8];
    const float* lBv   = (const float*)d_in[9];
    const int*   step  = (const int*)d_in[10];
    float* out = (float*)d_out;

    float *q, *k, *v, *y, *tq, *tv;
    cudaGetSymbolAddress((void**)&q,  g_q);
    cudaGetSymbolAddress((void**)&k,  g_k);
    cudaGetSymbolAddress((void**)&v,  g_v);
    cudaGetSymbolAddress((void**)&y,  g_y);
    cudaGetSymbolAddress((void**)&tq, g_tq);
    cudaGetSymbolAddress((void**)&tv, g_tv);

    const int M = MTOT;

    // projections
    sgemm_abt<<<dim3(DIM / BN, M / BM), 256>>>(x, Wq, q, M, DIM, DIM);
    sgemm_abt<<<dim3(KV_DIM / BN, M / BM), 256>>>(x, Wk, k, M, KV_DIM, DIM);
    sgemm_abt<<<dim3(KV_DIM / BN, M / BM), 256>>>(x, Wv, v, M, KV_DIM, DIM);

    // LoRA (step-dependent on device)
    lora_down<<<M, 128>>>(x, lAq, step, tq, DIM);
    lora_down<<<M, 128>>>(x, lAv, step, tv, DIM);
    lora_up<<<(M * DIM + 255) / 256, 256>>>(tq, lBq, step, q, M, DIM, 1.0f);
    lora_up<<<(M * KV_DIM + 255) / 256, 256>>>(tv, lBv, step, v, M, KV_DIM, 1.0f);

    // per-head RMSNorm + partial RoPE (+ gain on q)
    rmsnorm_rope<<<(M * NUM_HEADS + 7) / 8, 256>>>(q, qgain, NUM_HEADS, M * NUM_HEADS);
    rmsnorm_rope<<<(M * NUM_KV_HEADS + 7) / 8, 256>>>(k, nullptr, NUM_KV_HEADS, M * NUM_KV_HEADS);

    // causal GQA attention
    static bool attr_set = false;
    if (!attr_set) {
        cudaFuncSetAttribute(attn_kernel, cudaFuncAttributeMaxDynamicSharedMemorySize, 49152);
        attr_set = true;
    }
    attn_kernel<<<dim3(SEQ / 64, NUM_HEADS, BATCH), 256, 49152>>>(q, k, v, y);

    // output projection
    sgemm_abt<<<dim3(DIM / BN, M / BM), 256>>>(y, Wproj, out, M, DIM, DIM);
}